// round 1
// baseline (speedup 1.0000x reference)
#include <cuda_runtime.h>
#include <cuda_bf16.h>

#define N_NODES 100000
#define N_EDGES 1600000
#define D 128
#define KTOT 256              // concat(self, neigh) reduction dim
#define IRS 260               // padded input-tile row stride (floats): bank-conflict-free a-loads
#define TILE_R 64
#define GEMM_THREADS 256
#define SMEM_BYTES (KTOT*D*4 + TILE_R*IRS*4 + D*4)   // 131072 + 66560 + 512 = 198144

// ---------------- device scratch (no allocations allowed) ----------------
__device__ __align__(16) float g_deg[N_NODES];
__device__ __align__(16) float g_agg[(size_t)N_NODES * D];
__device__ __align__(16) float g_h1[(size_t)N_NODES * D];
__device__ __align__(16) float g_wcat1[KTOT * D];
__device__ __align__(16) float g_wcat2[KTOT * D];

// ---------------- f32x2 helpers (Blackwell packed fp32) ----------------
__device__ __forceinline__ unsigned long long ffma2(unsigned long long a,
                                                    unsigned long long b,
                                                    unsigned long long c) {
    unsigned long long d;
    asm("fma.rn.f32x2 %0, %1, %2, %3;" : "=l"(d) : "l"(a), "l"(b), "l"(c));
    return d;
}
__device__ __forceinline__ unsigned long long pack2(float x) {
    unsigned long long d;
    asm("mov.b64 %0, {%1, %1};" : "=l"(d) : "f"(x));
    return d;
}
__device__ __forceinline__ float2 unpack2(unsigned long long v) {
    float2 r;
    asm("mov.b64 {%0, %1}, %2;" : "=f"(r.x), "=f"(r.y) : "l"(v));
    return r;
}

// ---------------- utility kernels ----------------
__global__ void zero4_kernel(float4* __restrict__ p, int n4) {
    int i = blockIdx.x * blockDim.x + threadIdx.x;
    if (i < n4) p[i] = make_float4(0.f, 0.f, 0.f, 0.f);
}

__global__ void deg_kernel(const int* __restrict__ dst, float* __restrict__ deg) {
    int e = blockIdx.x * blockDim.x + threadIdx.x;
    if (e < N_EDGES) atomicAdd(&deg[dst[e]], 1.0f);
}

// Build transposed concat weight: wcat[k*128 + j] = (k<128 ? Ws[j][k] : Wn[j][k-128])
__global__ void wcat_kernel(const float* __restrict__ Ws, const float* __restrict__ Wn,
                            float* __restrict__ wcat) {
    int idx = blockIdx.x * blockDim.x + threadIdx.x;   // idx = j*256 + k  (coalesced reads)
    if (idx >= D * KTOT) return;
    int j = idx >> 8;
    int k = idx & 255;
    float v = (k < D) ? Ws[j * D + k] : Wn[j * D + (k - D)];
    wcat[k * D + j] = v;
}

// Edge aggregation: agg[dst] += feat[src], one warp per edge, float4 atomics
__global__ void agg_kernel(const float* __restrict__ feat,
                           const int* __restrict__ src, const int* __restrict__ dst,
                           float* __restrict__ agg) {
    unsigned int idx = blockIdx.x * blockDim.x + threadIdx.x;
    if (idx >= (unsigned int)N_EDGES * 32u) return;
    unsigned int e = idx >> 5;
    unsigned int c = (idx & 31u) << 2;
    int s = __ldg(&src[e]);
    int d = __ldg(&dst[e]);
    float4 v = *(const float4*)(feat + (size_t)s * D + c);
    atomicAdd((float4*)(agg + (size_t)d * D + c), v);
}

// Fused SAGE layer: out = feat @ Wself^T + (agg/deg) @ Wneigh^T + b  [+ row L2-normalize]
// Persistent blocks; block tile = 64 rows x 128 cols, K = 256 (concat).
// Thread tile = 4 rows x 8 cols, accumulators in packed f32x2.
__global__ void __launch_bounds__(GEMM_THREADS, 1)
sage_gemm_kernel(const float* __restrict__ feat,
                 const float* __restrict__ wcat,     // [256][128] transposed concat
                 const float* __restrict__ bias,
                 const float* __restrict__ agg,
                 const float* __restrict__ deg,
                 float* __restrict__ out,
                 int do_norm) {
    extern __shared__ float smem[];
    float* sw   = smem;                  // [256][128]
    float* sinp = smem + KTOT * D;       // [64][IRS]
    float* sb   = sinp + TILE_R * IRS;   // [128]

    const int tid = threadIdx.x;

    // Load transposed weights (coalesced, contiguous STS)
    {
        const float4* wsrc = (const float4*)wcat;
        float4* wdst = (float4*)sw;
        for (int i = tid; i < (KTOT * D) / 4; i += GEMM_THREADS) wdst[i] = wsrc[i];
    }
    if (tid < D) sb[tid] = bias[tid];
    __syncthreads();

    const int ct = tid & 15;      // 16 col-thread groups, 8 cols each
    const int rt = tid >> 4;      // 16 row-thread groups, 4 rows each
    const int j0 = ct * 8;
    const int r0 = rt * 4;
    const int NT = (N_NODES + TILE_R - 1) / TILE_R;

    for (int tile = blockIdx.x; tile < NT; tile += gridDim.x) {
        const int row0 = tile * TILE_R;

        // ---- stage input tile: [x_row | agg_row/deg] -> sinp[r][k] ----
        for (int idx = tid; idx < TILE_R * (KTOT / 4); idx += GEMM_THREADS) {
            int r = idx >> 6;
            int q = idx & 63;      // float4 index along K=256
            int grow = row0 + r;
            float4 v = make_float4(0.f, 0.f, 0.f, 0.f);
            if (grow < N_NODES) {
                if (q < 32) {
                    v = *(const float4*)(feat + (size_t)grow * D + (q << 2));
                } else {
                    float inv = 1.0f / fmaxf(deg[grow], 1.0f);
                    v = *(const float4*)(agg + (size_t)grow * D + ((q - 32) << 2));
                    v.x *= inv; v.y *= inv; v.z *= inv; v.w *= inv;
                }
            }
            *(float4*)(sinp + r * IRS + (q << 2)) = v;
        }
        __syncthreads();

        // ---- main K loop: 16 FFMA2 / k / thread ----
        unsigned long long acc[16];
#pragma unroll
        for (int i = 0; i < 16; i++) acc[i] = 0ull;

        const float* a0 = sinp + r0 * IRS;
#pragma unroll 2
        for (int k = 0; k < KTOT; ++k) {
            const float* wk = sw + (k << 7) + j0;
            ulonglong2 wA = *(const ulonglong2*)(wk);
            ulonglong2 wB = *(const ulonglong2*)(wk + 4);
#pragma unroll
            for (int r = 0; r < 4; ++r) {
                unsigned long long av = pack2(a0[r * IRS + k]);
                acc[r * 4 + 0] = ffma2(av, wA.x, acc[r * 4 + 0]);
                acc[r * 4 + 1] = ffma2(av, wA.y, acc[r * 4 + 1]);
                acc[r * 4 + 2] = ffma2(av, wB.x, acc[r * 4 + 2]);
                acc[r * 4 + 3] = ffma2(av, wB.y, acc[r * 4 + 3]);
            }
        }

        // ---- epilogue: bias (+ optional fused row-L2-normalize) ----
#pragma unroll
        for (int r = 0; r < 4; ++r) {
            float v[8];
            float2 t;
            t = unpack2(acc[r * 4 + 0]); v[0] = t.x; v[1] = t.y;
            t = unpack2(acc[r * 4 + 1]); v[2] = t.x; v[3] = t.y;
            t = unpack2(acc[r * 4 + 2]); v[4] = t.x; v[5] = t.y;
            t = unpack2(acc[r * 4 + 3]); v[6] = t.x; v[7] = t.y;
#pragma unroll
            for (int c = 0; c < 8; c++) v[c] += sb[j0 + c];

            float scale = 1.0f;
            if (do_norm) {
                float ss = 0.f;
#pragma unroll
                for (int c = 0; c < 8; c++) ss += v[c] * v[c];
#pragma unroll
                for (int m = 8; m >= 1; m >>= 1)
                    ss += __shfl_xor_sync(0xffffffffu, ss, m);
                scale = 1.0f / fmaxf(sqrtf(ss), 1e-12f);
            }

            int grow = row0 + r0 + r;
            if (grow < N_NODES) {
                float* op = out + (size_t)grow * D + j0;
                float4 o;
                o.x = v[0] * scale; o.y = v[1] * scale;
                o.z = v[2] * scale; o.w = v[3] * scale;
                *(float4*)op = o;
                o.x = v[4] * scale; o.y = v[5] * scale;
                o.z = v[6] * scale; o.w = v[7] * scale;
                *(float4*)(op + 4) = o;
            }
        }
        __syncthreads();
    }
}

// ---------------- launch ----------------
extern "C" void kernel_launch(void* const* d_in, const int* in_sizes, int n_in,
                              void* d_out, int out_size) {
    const float* x   = (const float*)d_in[0];
    const int* src   = (const int*)d_in[1];
    const int* dst   = (const int*)d_in[2];
    const float* Ws1 = (const float*)d_in[3];
    const float* Wn1 = (const float*)d_in[4];
    const float* b1  = (const float*)d_in[5];
    const float* Ws2 = (const float*)d_in[6];
    const float* Wn2 = (const float*)d_in[7];
    const float* b2  = (const float*)d_in[8];
    float* out = (float*)d_out;

    float* deg;   cudaGetSymbolAddress((void**)&deg, g_deg);
    float* agg;   cudaGetSymbolAddress((void**)&agg, g_agg);
    float* h1;    cudaGetSymbolAddress((void**)&h1, g_h1);
    float* wcat1; cudaGetSymbolAddress((void**)&wcat1, g_wcat1);
    float* wcat2; cudaGetSymbolAddress((void**)&wcat2, g_wcat2);

    int sms = 148;
    cudaDeviceGetAttribute(&sms, cudaDevAttrMultiProcessorCount, 0);
    cudaFuncSetAttribute(sage_gemm_kernel,
                         cudaFuncAttributeMaxDynamicSharedMemorySize, SMEM_BYTES);

    const int AGG_ITEMS = N_EDGES * 32;

    // degrees + weight transposes
    zero4_kernel<<<(N_NODES / 4 + 255) / 256, 256>>>((float4*)deg, N_NODES / 4);
    zero4_kernel<<<(N_NODES * D / 4 + 255) / 256, 256>>>((float4*)agg, N_NODES * D / 4);
    deg_kernel<<<(N_EDGES + 255) / 256, 256>>>(dst, deg);
    wcat_kernel<<<(KTOT * D + 255) / 256, 256>>>(Ws1, Wn1, wcat1);
    wcat_kernel<<<(KTOT * D + 255) / 256, 256>>>(Ws2, Wn2, wcat2);

    // layer 1
    agg_kernel<<<(AGG_ITEMS + 255) / 256, 256>>>(x, src, dst, agg);
    sage_gemm_kernel<<<sms, GEMM_THREADS, SMEM_BYTES>>>(x, wcat1, b1, agg, deg, h1, 0);

    // layer 2
    zero4_kernel<<<(N_NODES * D / 4 + 255) / 256, 256>>>((float4*)agg, N_NODES * D / 4);
    agg_kernel<<<(AGG_ITEMS + 255) / 256, 256>>>(h1, src, dst, agg);
    sage_gemm_kernel<<<sms, GEMM_THREADS, SMEM_BYTES>>>(h1, wcat2, b2, agg, deg, out, 1);
}

// round 2
// speedup vs baseline: 1.1683x; 1.1683x over previous
#include <cuda_runtime.h>
#include <cuda_bf16.h>

#define N_NODES 100000
#define N_EDGES 1600000
#define D 128
#define KTOT 256              // concat(self, neigh) reduction dim
#define IRS 260               // padded input-tile row stride (floats)
#define TILE_R 64
#define GEMM_THREADS 256
#define SMEM_BYTES (KTOT*D*4 + TILE_R*IRS*4 + D*4)   // 198144

// ---------------- device scratch (no allocations allowed) ----------------
__device__ __align__(16) float g_agg[(size_t)N_NODES * D];
__device__ __align__(16) float g_h1[(size_t)N_NODES * D];
__device__ __align__(16) float g_wcat1[KTOT * D];
__device__ __align__(16) float g_wcat2[KTOT * D];
__device__ __align__(16) int   g_degi[N_NODES];
__device__ __align__(16) int   g_rowstart[N_NODES];
__device__ __align__(16) int   g_cursor[N_NODES];
__device__ __align__(16) int   g_col[N_EDGES];

// ---------------- f32x2 helpers (Blackwell packed fp32) ----------------
__device__ __forceinline__ unsigned long long ffma2(unsigned long long a,
                                                    unsigned long long b,
                                                    unsigned long long c) {
    unsigned long long d;
    asm("fma.rn.f32x2 %0, %1, %2, %3;" : "=l"(d) : "l"(a), "l"(b), "l"(c));
    return d;
}
__device__ __forceinline__ unsigned long long pack2(float x) {
    unsigned long long d;
    asm("mov.b64 %0, {%1, %1};" : "=l"(d) : "f"(x));
    return d;
}
__device__ __forceinline__ float2 unpack2(unsigned long long v) {
    float2 r;
    asm("mov.b64 {%0, %1}, %2;" : "=f"(r.x), "=f"(r.y) : "l"(v));
    return r;
}

// ---------------- CSR build ----------------
__global__ void zeroi_kernel(int* __restrict__ p, int n) {
    int i = blockIdx.x * blockDim.x + threadIdx.x;
    if (i < n) p[i] = 0;
}

__global__ void degi_kernel(const int* __restrict__ dst, int* __restrict__ deg) {
    int e = blockIdx.x * blockDim.x + threadIdx.x;
    if (e < N_EDGES) atomicAdd(&deg[dst[e]], 1);
}

// Single-block chunked exclusive scan of deg -> row_start (and cursor copy)
__global__ void scan_kernel(const int* __restrict__ deg,
                            int* __restrict__ row_start, int* __restrict__ cursor) {
    __shared__ int ssum[1024];
    const int t = threadIdx.x;
    const int CH = (N_NODES + 1023) / 1024;     // 98
    const int lo = t * CH;
    const int hi = (lo + CH < N_NODES) ? lo + CH : N_NODES;
    int s = 0;
    for (int i = lo; i < hi; i++) s += deg[i];
    ssum[t] = s;
    __syncthreads();
    // Hillis-Steele inclusive scan over 1024 chunk sums
    for (int off = 1; off < 1024; off <<= 1) {
        int v = (t >= off) ? ssum[t - off] : 0;
        __syncthreads();
        ssum[t] += v;
        __syncthreads();
    }
    int run = (t == 0) ? 0 : ssum[t - 1];
    for (int i = lo; i < hi; i++) {
        row_start[i] = run;
        cursor[i] = run;
        run += deg[i];
    }
}

__global__ void fill_kernel(const int* __restrict__ src, const int* __restrict__ dst,
                            int* __restrict__ cursor, int* __restrict__ col) {
    int e = blockIdx.x * blockDim.x + threadIdx.x;
    if (e < N_EDGES) {
        int d = dst[e];
        int p = atomicAdd(&cursor[d], 1);
        col[p] = src[e];
    }
}

// ---------------- gather-mean aggregation: one warp per node ----------------
__global__ void gather_kernel(const float* __restrict__ feat,
                              const int* __restrict__ row_start,
                              const int* __restrict__ degi,
                              const int* __restrict__ col,
                              float* __restrict__ agg) {
    int warp = (blockIdx.x * blockDim.x + threadIdx.x) >> 5;
    if (warp >= N_NODES) return;
    const int lane = threadIdx.x & 31;
    const int c4 = lane << 2;
    const int start = row_start[warp];
    const int len = degi[warp];
    const int end = start + len;

    float4 acc = make_float4(0.f, 0.f, 0.f, 0.f);
    int e = start;
    for (; e + 4 <= end; e += 4) {
        int s0 = __ldg(&col[e + 0]);
        int s1 = __ldg(&col[e + 1]);
        int s2 = __ldg(&col[e + 2]);
        int s3 = __ldg(&col[e + 3]);
        float4 v0 = *(const float4*)(feat + (size_t)s0 * D + c4);
        float4 v1 = *(const float4*)(feat + (size_t)s1 * D + c4);
        float4 v2 = *(const float4*)(feat + (size_t)s2 * D + c4);
        float4 v3 = *(const float4*)(feat + (size_t)s3 * D + c4);
        acc.x += (v0.x + v1.x) + (v2.x + v3.x);
        acc.y += (v0.y + v1.y) + (v2.y + v3.y);
        acc.z += (v0.z + v1.z) + (v2.z + v3.z);
        acc.w += (v0.w + v1.w) + (v2.w + v3.w);
    }
    for (; e < end; e++) {
        int s = __ldg(&col[e]);
        float4 v = *(const float4*)(feat + (size_t)s * D + c4);
        acc.x += v.x; acc.y += v.y; acc.z += v.z; acc.w += v.w;
    }
    const float inv = 1.0f / fmaxf((float)len, 1.0f);
    float4 o;
    o.x = acc.x * inv; o.y = acc.y * inv; o.z = acc.z * inv; o.w = acc.w * inv;
    *(float4*)(agg + (size_t)warp * D + c4) = o;
}

// ---------------- weight transpose/concat ----------------
__global__ void wcat_kernel(const float* __restrict__ Ws, const float* __restrict__ Wn,
                            float* __restrict__ wcat) {
    int idx = blockIdx.x * blockDim.x + threadIdx.x;   // idx = j*256 + k
    if (idx >= D * KTOT) return;
    int j = idx >> 8;
    int k = idx & 255;
    float v = (k < D) ? Ws[j * D + k] : Wn[j * D + (k - D)];
    wcat[k * D + j] = v;
}

// ---------------- fused SAGE GEMM: out = [feat|mean] @ wcat + b (+L2norm) ----
__global__ void __launch_bounds__(GEMM_THREADS, 1)
sage_gemm_kernel(const float* __restrict__ feat,
                 const float* __restrict__ wcat,     // [256][128]
                 const float* __restrict__ bias,
                 const float* __restrict__ agg,      // already mean-normalized
                 float* __restrict__ out,
                 int do_norm) {
    extern __shared__ float smem[];
    float* sw   = smem;                  // [256][128]
    float* sinp = smem + KTOT * D;       // [64][IRS]
    float* sb   = sinp + TILE_R * IRS;   // [128]

    const int tid = threadIdx.x;

    {
        const float4* wsrc = (const float4*)wcat;
        float4* wdst = (float4*)sw;
        for (int i = tid; i < (KTOT * D) / 4; i += GEMM_THREADS) wdst[i] = wsrc[i];
    }
    if (tid < D) sb[tid] = bias[tid];
    __syncthreads();

    const int ct = tid & 15;
    const int rt = tid >> 4;
    const int j0 = ct * 8;
    const int r0 = rt * 4;
    const int NT = (N_NODES + TILE_R - 1) / TILE_R;

    for (int tile = blockIdx.x; tile < NT; tile += gridDim.x) {
        const int row0 = tile * TILE_R;

        for (int idx = tid; idx < TILE_R * (KTOT / 4); idx += GEMM_THREADS) {
            int r = idx >> 6;
            int q = idx & 63;
            int grow = row0 + r;
            float4 v = make_float4(0.f, 0.f, 0.f, 0.f);
            if (grow < N_NODES) {
                if (q < 32)
                    v = *(const float4*)(feat + (size_t)grow * D + (q << 2));
                else
                    v = *(const float4*)(agg + (size_t)grow * D + ((q - 32) << 2));
            }
            *(float4*)(sinp + r * IRS + (q << 2)) = v;
        }
        __syncthreads();

        unsigned long long acc[16];
#pragma unroll
        for (int i = 0; i < 16; i++) acc[i] = 0ull;

        const float* a0 = sinp + r0 * IRS;
#pragma unroll 2
        for (int k = 0; k < KTOT; ++k) {
            const float* wk = sw + (k << 7) + j0;
            ulonglong2 wA = *(const ulonglong2*)(wk);
            ulonglong2 wB = *(const ulonglong2*)(wk + 4);
#pragma unroll
            for (int r = 0; r < 4; ++r) {
                unsigned long long av = pack2(a0[r * IRS + k]);
                acc[r * 4 + 0] = ffma2(av, wA.x, acc[r * 4 + 0]);
                acc[r * 4 + 1] = ffma2(av, wA.y, acc[r * 4 + 1]);
                acc[r * 4 + 2] = ffma2(av, wB.x, acc[r * 4 + 2]);
                acc[r * 4 + 3] = ffma2(av, wB.y, acc[r * 4 + 3]);
            }
        }

#pragma unroll
        for (int r = 0; r < 4; ++r) {
            float v[8];
            float2 t;
            t = unpack2(acc[r * 4 + 0]); v[0] = t.x; v[1] = t.y;
            t = unpack2(acc[r * 4 + 1]); v[2] = t.x; v[3] = t.y;
            t = unpack2(acc[r * 4 + 2]); v[4] = t.x; v[5] = t.y;
            t = unpack2(acc[r * 4 + 3]); v[6] = t.x; v[7] = t.y;
#pragma unroll
            for (int c = 0; c < 8; c++) v[c] += sb[j0 + c];

            float scale = 1.0f;
            if (do_norm) {
                float ss = 0.f;
#pragma unroll
                for (int c = 0; c < 8; c++) ss += v[c] * v[c];
#pragma unroll
                for (int m = 8; m >= 1; m >>= 1)
                    ss += __shfl_xor_sync(0xffffffffu, ss, m);
                scale = 1.0f / fmaxf(sqrtf(ss), 1e-12f);
            }

            int grow = row0 + r0 + r;
            if (grow < N_NODES) {
                float* op = out + (size_t)grow * D + j0;
                float4 o;
                o.x = v[0] * scale; o.y = v[1] * scale;
                o.z = v[2] * scale; o.w = v[3] * scale;
                *(float4*)op = o;
                o.x = v[4] * scale; o.y = v[5] * scale;
                o.z = v[6] * scale; o.w = v[7] * scale;
                *(float4*)(op + 4) = o;
            }
        }
        __syncthreads();
    }
}

// ---------------- launch ----------------
extern "C" void kernel_launch(void* const* d_in, const int* in_sizes, int n_in,
                              void* d_out, int out_size) {
    const float* x   = (const float*)d_in[0];
    const int* src   = (const int*)d_in[1];
    const int* dst   = (const int*)d_in[2];
    const float* Ws1 = (const float*)d_in[3];
    const float* Wn1 = (const float*)d_in[4];
    const float* b1  = (const float*)d_in[5];
    const float* Ws2 = (const float*)d_in[6];
    const float* Wn2 = (const float*)d_in[7];
    const float* b2  = (const float*)d_in[8];
    float* out = (float*)d_out;

    float* agg;   cudaGetSymbolAddress((void**)&agg, g_agg);
    float* h1;    cudaGetSymbolAddress((void**)&h1, g_h1);
    float* wcat1; cudaGetSymbolAddress((void**)&wcat1, g_wcat1);
    float* wcat2; cudaGetSymbolAddress((void**)&wcat2, g_wcat2);
    int* degi;    cudaGetSymbolAddress((void**)&degi, g_degi);
    int* rowst;   cudaGetSymbolAddress((void**)&rowst, g_rowstart);
    int* cursor;  cudaGetSymbolAddress((void**)&cursor, g_cursor);
    int* col;     cudaGetSymbolAddress((void**)&col, g_col);

    int sms = 148;
    cudaDeviceGetAttribute(&sms, cudaDevAttrMultiProcessorCount, 0);
    cudaFuncSetAttribute(sage_gemm_kernel,
                         cudaFuncAttributeMaxDynamicSharedMemorySize, SMEM_BYTES);

    // ---- CSR build (by dst) ----
    zeroi_kernel<<<(N_NODES + 255) / 256, 256>>>(degi, N_NODES);
    degi_kernel<<<(N_EDGES + 255) / 256, 256>>>(dst, degi);
    scan_kernel<<<1, 1024>>>(degi, rowst, cursor);
    fill_kernel<<<(N_EDGES + 255) / 256, 256>>>(src, dst, cursor, col);

    // ---- weight transposes ----
    wcat_kernel<<<(KTOT * D + 255) / 256, 256>>>(Ws1, Wn1, wcat1);
    wcat_kernel<<<(KTOT * D + 255) / 256, 256>>>(Ws2, Wn2, wcat2);

    const int GATHER_BLOCKS = (N_NODES * 32 + 255) / 256;

    // ---- layer 1 ----
    gather_kernel<<<GATHER_BLOCKS, 256>>>(x, rowst, degi, col, agg);
    sage_gemm_kernel<<<sms, GEMM_THREADS, SMEM_BYTES>>>(x, wcat1, b1, agg, h1, 0);

    // ---- layer 2 ----
    gather_kernel<<<GATHER_BLOCKS, 256>>>(h1, rowst, degi, col, agg);
    sage_gemm_kernel<<<sms, GEMM_THREADS, SMEM_BYTES>>>(h1, wcat2, b2, agg, out, 1);
}

// round 3
// speedup vs baseline: 1.1799x; 1.0099x over previous
#include <cuda_runtime.h>
#include <cuda_bf16.h>

#define N_NODES 100000
#define N_EDGES 1600000
#define D 128
#define KTOT 256              // concat(self, neigh) reduction dim
#define IRS 260               // padded input-tile row stride (floats)
#define TILE_R 64
#define GEMM_THREADS 256
#define SMEM_BYTES (KTOT*D*4 + TILE_R*IRS*4 + D*4)   // 198144

// ---------------- device scratch (no allocations allowed) ----------------
__device__ __align__(16) float g_agg[(size_t)N_NODES * D];
__device__ __align__(16) float g_h1[(size_t)N_NODES * D];
__device__ __align__(16) float g_wcat1[KTOT * D];
__device__ __align__(16) float g_wcat2[KTOT * D];
__device__ __align__(16) int   g_degi[N_NODES];
__device__ __align__(16) int   g_rowstart[N_NODES];
__device__ __align__(16) int   g_cursor[N_NODES];
__device__ __align__(16) int   g_col[N_EDGES];

// ---------------- f32x2 helpers (Blackwell packed fp32) ----------------
__device__ __forceinline__ unsigned long long ffma2(unsigned long long a,
                                                    unsigned long long b,
                                                    unsigned long long c) {
    unsigned long long d;
    asm("fma.rn.f32x2 %0, %1, %2, %3;" : "=l"(d) : "l"(a), "l"(b), "l"(c));
    return d;
}
__device__ __forceinline__ unsigned long long pack2(float x) {
    unsigned long long d;
    asm("mov.b64 %0, {%1, %1};" : "=l"(d) : "f"(x));
    return d;
}
__device__ __forceinline__ float2 unpack2(unsigned long long v) {
    float2 r;
    asm("mov.b64 {%0, %1}, %2;" : "=f"(r.x), "=f"(r.y) : "l"(v));
    return r;
}

// ---------------- CSR build ----------------
__global__ void zeroi_kernel(int* __restrict__ p, int n) {
    int i = blockIdx.x * blockDim.x + threadIdx.x;
    if (i < n) p[i] = 0;
}

__global__ void degi_kernel(const int* __restrict__ dst, int* __restrict__ deg) {
    int e = blockIdx.x * blockDim.x + threadIdx.x;
    if (e < N_EDGES) atomicAdd(&deg[dst[e]], 1);
}

// Single-block chunked exclusive scan of deg -> row_start (and cursor copy)
__global__ void scan_kernel(const int* __restrict__ deg,
                            int* __restrict__ row_start, int* __restrict__ cursor) {
    __shared__ int ssum[1024];
    const int t = threadIdx.x;
    const int CH = (N_NODES + 1023) / 1024;     // 98
    const int lo = t * CH;
    const int hi = (lo + CH < N_NODES) ? lo + CH : N_NODES;
    int s = 0;
    for (int i = lo; i < hi; i++) s += deg[i];
    ssum[t] = s;
    __syncthreads();
    // Hillis-Steele inclusive scan over 1024 chunk sums
    for (int off = 1; off < 1024; off <<= 1) {
        int v = (t >= off) ? ssum[t - off] : 0;
        __syncthreads();
        ssum[t] += v;
        __syncthreads();
    }
    int run = (t == 0) ? 0 : ssum[t - 1];
    for (int i = lo; i < hi; i++) {
        row_start[i] = run;
        cursor[i] = run;
        run += deg[i];
    }
}

__global__ void fill_kernel(const int* __restrict__ src, const int* __restrict__ dst,
                            int* __restrict__ cursor, int* __restrict__ col) {
    int e = blockIdx.x * blockDim.x + threadIdx.x;
    if (e < N_EDGES) {
        int d = dst[e];
        int p = atomicAdd(&cursor[d], 1);
        col[p] = src[e];
    }
}

// ---------------- gather-mean aggregation: one warp per node ----------------
__global__ void gather_kernel(const float* __restrict__ feat,
                              const int* __restrict__ row_start,
                              const int* __restrict__ degi,
                              const int* __restrict__ col,
                              float* __restrict__ agg) {
    int warp = (blockIdx.x * blockDim.x + threadIdx.x) >> 5;
    if (warp >= N_NODES) return;
    const int lane = threadIdx.x & 31;
    const int c4 = lane << 2;
    const int start = row_start[warp];
    const int len = degi[warp];
    const int end = start + len;

    float4 acc = make_float4(0.f, 0.f, 0.f, 0.f);
    int e = start;
    for (; e + 4 <= end; e += 4) {
        int s0 = __ldg(&col[e + 0]);
        int s1 = __ldg(&col[e + 1]);
        int s2 = __ldg(&col[e + 2]);
        int s3 = __ldg(&col[e + 3]);
        float4 v0 = *(const float4*)(feat + (size_t)s0 * D + c4);
        float4 v1 = *(const float4*)(feat + (size_t)s1 * D + c4);
        float4 v2 = *(const float4*)(feat + (size_t)s2 * D + c4);
        float4 v3 = *(const float4*)(feat + (size_t)s3 * D + c4);
        acc.x += (v0.x + v1.x) + (v2.x + v3.x);
        acc.y += (v0.y + v1.y) + (v2.y + v3.y);
        acc.z += (v0.z + v1.z) + (v2.z + v3.z);
        acc.w += (v0.w + v1.w) + (v2.w + v3.w);
    }
    for (; e < end; e++) {
        int s = __ldg(&col[e]);
        float4 v = *(const float4*)(feat + (size_t)s * D + c4);
        acc.x += v.x; acc.y += v.y; acc.z += v.z; acc.w += v.w;
    }
    const float inv = 1.0f / fmaxf((float)len, 1.0f);
    float4 o;
    o.x = acc.x * inv; o.y = acc.y * inv; o.z = acc.z * inv; o.w = acc.w * inv;
    *(float4*)(agg + (size_t)warp * D + c4) = o;
}

// ---------------- weight transpose/concat ----------------
__global__ void wcat_kernel(const float* __restrict__ Ws, const float* __restrict__ Wn,
                            float* __restrict__ wcat) {
    int idx = blockIdx.x * blockDim.x + threadIdx.x;   // idx = j*256 + k
    if (idx >= D * KTOT) return;
    int j = idx >> 8;
    int k = idx & 255;
    float v = (k < D) ? Ws[j * D + k] : Wn[j * D + (k - D)];
    wcat[k * D + j] = v;
}

// ---------------- fused SAGE GEMM: out = [feat|mean] @ wcat + b (+L2norm) ----
__global__ void __launch_bounds__(GEMM_THREADS, 1)
sage_gemm_kernel(const float* __restrict__ feat,
                 const float* __restrict__ wcat,     // [256][128]
                 const float* __restrict__ bias,
                 const float* __restrict__ agg,      // already mean-normalized
                 float* __restrict__ out,
                 int do_norm) {
    extern __shared__ float smem[];
    float* sw   = smem;                  // [256][128]
    float* sinp = smem + KTOT * D;       // [64][IRS]
    float* sb   = sinp + TILE_R * IRS;   // [128]

    const int tid = threadIdx.x;

    {
        const float4* wsrc = (const float4*)wcat;
        float4* wdst = (float4*)sw;
        for (int i = tid; i < (KTOT * D) / 4; i += GEMM_THREADS) wdst[i] = wsrc[i];
    }
    if (tid < D) sb[tid] = bias[tid];
    __syncthreads();

    const int ct = tid & 15;
    const int rt = tid >> 4;
    const int j0 = ct * 8;
    const int r0 = rt * 4;
    const int NT = (N_NODES + TILE_R - 1) / TILE_R;

    for (int tile = blockIdx.x; tile < NT; tile += gridDim.x) {
        const int row0 = tile * TILE_R;

        for (int idx = tid; idx < TILE_R * (KTOT / 4); idx += GEMM_THREADS) {
            int r = idx >> 6;
            int q = idx & 63;
            int grow = row0 + r;
            float4 v = make_float4(0.f, 0.f, 0.f, 0.f);
            if (grow < N_NODES) {
                if (q < 32)
                    v = *(const float4*)(feat + (size_t)grow * D + (q << 2));
                else
                    v = *(const float4*)(agg + (size_t)grow * D + ((q - 32) << 2));
            }
            *(float4*)(sinp + r * IRS + (q << 2)) = v;
        }
        __syncthreads();

        unsigned long long acc[16];
#pragma unroll
        for (int i = 0; i < 16; i++) acc[i] = 0ull;

        const float* a0 = sinp + r0 * IRS;
#pragma unroll 2
        for (int k = 0; k < KTOT; ++k) {
            const float* wk = sw + (k << 7) + j0;
            ulonglong2 wA = *(const ulonglong2*)(wk);
            ulonglong2 wB = *(const ulonglong2*)(wk + 4);
#pragma unroll
            for (int r = 0; r < 4; ++r) {
                unsigned long long av = pack2(a0[r * IRS + k]);
                acc[r * 4 + 0] = ffma2(av, wA.x, acc[r * 4 + 0]);
                acc[r * 4 + 1] = ffma2(av, wA.y, acc[r * 4 + 1]);
                acc[r * 4 + 2] = ffma2(av, wB.x, acc[r * 4 + 2]);
                acc[r * 4 + 3] = ffma2(av, wB.y, acc[r * 4 + 3]);
            }
        }

#pragma unroll
        for (int r = 0; r < 4; ++r) {
            float v[8];
            float2 t;
            t = unpack2(acc[r * 4 + 0]); v[0] = t.x; v[1] = t.y;
            t = unpack2(acc[r * 4 + 1]); v[2] = t.x; v[3] = t.y;
            t = unpack2(acc[r * 4 + 2]); v[4] = t.x; v[5] = t.y;
            t = unpack2(acc[r * 4 + 3]); v[6] = t.x; v[7] = t.y;
#pragma unroll
            for (int c = 0; c < 8; c++) v[c] += sb[j0 + c];

            float scale = 1.0f;
            if (do_norm) {
                float ss = 0.f;
#pragma unroll
                for (int c = 0; c < 8; c++) ss += v[c] * v[c];
#pragma unroll
                for (int m = 8; m >= 1; m >>= 1)
                    ss += __shfl_xor_sync(0xffffffffu, ss, m);
                scale = 1.0f / fmaxf(sqrtf(ss), 1e-12f);
            }

            int grow = row0 + r0 + r;
            if (grow < N_NODES) {
                float* op = out + (size_t)grow * D + j0;
                float4 o;
                o.x = v[0] * scale; o.y = v[1] * scale;
                o.z = v[2] * scale; o.w = v[3] * scale;
                *(float4*)op = o;
                o.x = v[4] * scale; o.y = v[5] * scale;
                o.z = v[6] * scale; o.w = v[7] * scale;
                *(float4*)(op + 4) = o;
            }
        }
        __syncthreads();
    }
}

// ---------------- launch ----------------
extern "C" void kernel_launch(void* const* d_in, const int* in_sizes, int n_in,
                              void* d_out, int out_size) {
    const float* x   = (const float*)d_in[0];
    const int* src   = (const int*)d_in[1];
    const int* dst   = (const int*)d_in[2];
    const float* Ws1 = (const float*)d_in[3];
    const float* Wn1 = (const float*)d_in[4];
    const float* b1  = (const float*)d_in[5];
    const float* Ws2 = (const float*)d_in[6];
    const float* Wn2 = (const float*)d_in[7];
    const float* b2  = (const float*)d_in[8];
    float* out = (float*)d_out;

    float* agg;   cudaGetSymbolAddress((void**)&agg, g_agg);
    float* h1;    cudaGetSymbolAddress((void**)&h1, g_h1);
    float* wcat1; cudaGetSymbolAddress((void**)&wcat1, g_wcat1);
    float* wcat2; cudaGetSymbolAddress((void**)&wcat2, g_wcat2);
    int* degi;    cudaGetSymbolAddress((void**)&degi, g_degi);
    int* rowst;   cudaGetSymbolAddress((void**)&rowst, g_rowstart);
    int* cursor;  cudaGetSymbolAddress((void**)&cursor, g_cursor);
    int* col;     cudaGetSymbolAddress((void**)&col, g_col);

    int sms = 148;
    cudaDeviceGetAttribute(&sms, cudaDevAttrMultiProcessorCount, 0);
    cudaFuncSetAttribute(sage_gemm_kernel,
                         cudaFuncAttributeMaxDynamicSharedMemorySize, SMEM_BYTES);

    // ---- CSR build (by dst) ----
    zeroi_kernel<<<(N_NODES + 255) / 256, 256>>>(degi, N_NODES);
    degi_kernel<<<(N_EDGES + 255) / 256, 256>>>(dst, degi);
    scan_kernel<<<1, 1024>>>(degi, rowst, cursor);
    fill_kernel<<<(N_EDGES + 255) / 256, 256>>>(src, dst, cursor, col);

    // ---- weight transposes ----
    wcat_kernel<<<(KTOT * D + 255) / 256, 256>>>(Ws1, Wn1, wcat1);
    wcat_kernel<<<(KTOT * D + 255) / 256, 256>>>(Ws2, Wn2, wcat2);

    const int GATHER_BLOCKS = (N_NODES * 32 + 255) / 256;

    // ---- layer 1 ----
    gather_kernel<<<GATHER_BLOCKS, 256>>>(x, rowst, degi, col, agg);
    sage_gemm_kernel<<<sms, GEMM_THREADS, SMEM_BYTES>>>(x, wcat1, b1, agg, h1, 0);

    // ---- layer 2 ----
    gather_kernel<<<GATHER_BLOCKS, 256>>>(h1, rowst, degi, col, agg);
    sage_gemm_kernel<<<sms, GEMM_THREADS, SMEM_BYTES>>>(h1, wcat2, b2, agg, out, 1);
}

// round 4
// speedup vs baseline: 1.2159x; 1.0305x over previous
#include <cuda_runtime.h>
#include <cuda_bf16.h>

#define N_NODES 100000
#define N_EDGES 1600000
#define D 128
#define KTOT 256
#define IRS 260
#define TILE_R 64
#define GEMM_THREADS 128
#define SMEM_BYTES (KTOT*D*4 + TILE_R*IRS*4 + D*4)   // 198144

#define SCAN_CHUNK 256
#define NBLK_SCAN ((N_NODES + SCAN_CHUNK - 1) / SCAN_CHUNK)   // 391

// ---------------- device scratch ----------------
__device__ __align__(16) float g_agg[(size_t)N_NODES * D];
__device__ __align__(16) float g_h1[(size_t)N_NODES * D];
__device__ __align__(16) float g_wcat1[KTOT * D];
__device__ __align__(16) float g_wcat2[KTOT * D];
__device__ __align__(16) int   g_degi[N_NODES];
__device__ __align__(16) int   g_rowstart[N_NODES];
__device__ __align__(16) int   g_cursor[N_NODES];
__device__ __align__(16) int   g_col[N_EDGES];
__device__ __align__(16) int   g_bsum[NBLK_SCAN];
__device__ __align__(16) int   g_boff[NBLK_SCAN];

// ---------------- f32x2 helpers ----------------
__device__ __forceinline__ unsigned long long ffma2(unsigned long long a,
                                                    unsigned long long b,
                                                    unsigned long long c) {
    unsigned long long d;
    asm("fma.rn.f32x2 %0, %1, %2, %3;" : "=l"(d) : "l"(a), "l"(b), "l"(c));
    return d;
}
__device__ __forceinline__ unsigned long long pack2(float x) {
    unsigned long long d;
    asm("mov.b64 %0, {%1, %1};" : "=l"(d) : "f"(x));
    return d;
}
__device__ __forceinline__ float2 unpack2(unsigned long long v) {
    float2 r;
    asm("mov.b64 {%0, %1}, %2;" : "=f"(r.x), "=f"(r.y) : "l"(v));
    return r;
}

// ---------------- CSR build ----------------
__global__ void zeroi_kernel(int* __restrict__ p, int n) {
    int i = blockIdx.x * blockDim.x + threadIdx.x;
    if (i < n) p[i] = 0;
}

__global__ void degi_kernel(const int* __restrict__ dst, int* __restrict__ deg) {
    int e = blockIdx.x * blockDim.x + threadIdx.x;
    if (e < N_EDGES) atomicAdd(&deg[dst[e]], 1);
}

// phase A: per-block sums of deg (coalesced)
__global__ void blocksum_kernel(const int* __restrict__ deg, int* __restrict__ bsum) {
    __shared__ int warp_s[8];
    int b = blockIdx.x;
    int i = b * SCAN_CHUNK + threadIdx.x;
    int v = (i < N_NODES) ? deg[i] : 0;
#pragma unroll
    for (int m = 16; m >= 1; m >>= 1) v += __shfl_xor_sync(0xffffffffu, v, m);
    if ((threadIdx.x & 31) == 0) warp_s[threadIdx.x >> 5] = v;
    __syncthreads();
    if (threadIdx.x == 0) {
        int s = 0;
#pragma unroll
        for (int w = 0; w < 8; w++) s += warp_s[w];
        bsum[b] = s;
    }
}

// phase B: single-block exclusive scan of 391 block sums
__global__ void scanbsum_kernel(const int* __restrict__ bsum, int* __restrict__ boff) {
    __shared__ int s[512];
    int t = threadIdx.x;
    s[t] = (t < NBLK_SCAN) ? bsum[t] : 0;
    __syncthreads();
    for (int off = 1; off < 512; off <<= 1) {
        int v = (t >= off) ? s[t - off] : 0;
        __syncthreads();
        s[t] += v;
        __syncthreads();
    }
    if (t < NBLK_SCAN) boff[t] = (t == 0) ? 0 : s[t - 1];
}

// phase C: per-block exclusive scan + base offset -> rowstart, cursor
__global__ void scanfinal_kernel(const int* __restrict__ deg, const int* __restrict__ boff,
                                 int* __restrict__ rowstart, int* __restrict__ cursor) {
    __shared__ int warp_s[8];
    int b = blockIdx.x;
    int t = threadIdx.x;
    int lane = t & 31, w = t >> 5;
    int i = b * SCAN_CHUNK + t;
    int v = (i < N_NODES) ? deg[i] : 0;
    // inclusive warp scan
    int sc = v;
#pragma unroll
    for (int m = 1; m < 32; m <<= 1) {
        int u = __shfl_up_sync(0xffffffffu, sc, m);
        if (lane >= m) sc += u;
    }
    if (lane == 31) warp_s[w] = sc;
    __syncthreads();
    int wbase = 0;
#pragma unroll
    for (int q = 0; q < 8; q++) wbase += (q < w) ? warp_s[q] : 0;
    int excl = boff[b] + wbase + sc - v;
    if (i < N_NODES) { rowstart[i] = excl; cursor[i] = excl; }
}

__global__ void fill_kernel(const int* __restrict__ src, const int* __restrict__ dst,
                            int* __restrict__ cursor, int* __restrict__ col) {
    int e = blockIdx.x * blockDim.x + threadIdx.x;
    if (e < N_EDGES) {
        int d = dst[e];
        int p = atomicAdd(&cursor[d], 1);
        col[p] = src[e];
    }
}

// ---------------- gather-mean: one warp per node, MLP=8 ----------------
__global__ void gather_kernel(const float* __restrict__ feat,
                              const int* __restrict__ row_start,
                              const int* __restrict__ degi,
                              const int* __restrict__ col,
                              float* __restrict__ agg) {
    int warp = (blockIdx.x * blockDim.x + threadIdx.x) >> 5;
    if (warp >= N_NODES) return;
    const int lane = threadIdx.x & 31;
    const int c4 = lane << 2;
    const int start = row_start[warp];
    const int len = degi[warp];
    const int end = start + len;

    float4 accA = make_float4(0.f, 0.f, 0.f, 0.f);
    float4 accB = make_float4(0.f, 0.f, 0.f, 0.f);
    int e = start;
    for (; e + 8 <= end; e += 8) {
        int s[8];
#pragma unroll
        for (int u = 0; u < 8; u++) s[u] = __ldg(&col[e + u]);
        float4 v[8];
#pragma unroll
        for (int u = 0; u < 8; u++)
            v[u] = *(const float4*)(feat + (size_t)s[u] * D + c4);
#pragma unroll
        for (int u = 0; u < 4; u++) {
            accA.x += v[u].x; accA.y += v[u].y; accA.z += v[u].z; accA.w += v[u].w;
            accB.x += v[u+4].x; accB.y += v[u+4].y; accB.z += v[u+4].z; accB.w += v[u+4].w;
        }
    }
    for (; e < end; e++) {
        int s = __ldg(&col[e]);
        float4 v = *(const float4*)(feat + (size_t)s * D + c4);
        accA.x += v.x; accA.y += v.y; accA.z += v.z; accA.w += v.w;
    }
    const float inv = 1.0f / fmaxf((float)len, 1.0f);
    float4 o;
    o.x = (accA.x + accB.x) * inv; o.y = (accA.y + accB.y) * inv;
    o.z = (accA.z + accB.z) * inv; o.w = (accA.w + accB.w) * inv;
    // streaming store: don't let agg evict feat from L2
    __stcs((float4*)(agg + (size_t)warp * D + c4), o);
}

// ---------------- weight transpose/concat ----------------
__global__ void wcat_kernel(const float* __restrict__ Ws, const float* __restrict__ Wn,
                            float* __restrict__ wcat) {
    int idx = blockIdx.x * blockDim.x + threadIdx.x;
    if (idx >= D * KTOT) return;
    int j = idx >> 8;
    int k = idx & 255;
    float v = (k < D) ? Ws[j * D + k] : Wn[j * D + (k - D)];
    wcat[k * D + j] = v;
}

// ---------------- fused SAGE GEMM: 128 thr, 8 rows x 8 cols / thread --------
__global__ void __launch_bounds__(GEMM_THREADS, 1)
sage_gemm_kernel(const float* __restrict__ feat,
                 const float* __restrict__ wcat,
                 const float* __restrict__ bias,
                 const float* __restrict__ agg,
                 float* __restrict__ out,
                 int do_norm) {
    extern __shared__ float smem[];
    float* sw   = smem;                  // [256][128]
    float* sinp = smem + KTOT * D;       // [64][IRS]
    float* sb   = sinp + TILE_R * IRS;   // [128]

    const int tid = threadIdx.x;

    {
        const float4* wsrc = (const float4*)wcat;
        float4* wdst = (float4*)sw;
#pragma unroll 4
        for (int i = tid; i < (KTOT * D) / 4; i += GEMM_THREADS) wdst[i] = wsrc[i];
    }
    if (tid < D) sb[tid] = bias[tid];
    __syncthreads();

    const int ct = tid & 15;      // 16 col groups x 8 cols
    const int rt = tid >> 4;      // 8 row groups x 8 rows
    const int j0 = ct * 8;
    const int r0 = rt * 8;
    const int NT = (N_NODES + TILE_R - 1) / TILE_R;

    for (int tile = blockIdx.x; tile < NT; tile += gridDim.x) {
        const int row0 = tile * TILE_R;

        // stage [feat | mean-agg] tile
#pragma unroll 4
        for (int idx = tid; idx < TILE_R * (KTOT / 4); idx += GEMM_THREADS) {
            int r = idx >> 6;
            int q = idx & 63;
            int grow = row0 + r;
            float4 v = make_float4(0.f, 0.f, 0.f, 0.f);
            if (grow < N_NODES) {
                if (q < 32)
                    v = *(const float4*)(feat + (size_t)grow * D + (q << 2));
                else
                    v = __ldcs((const float4*)(agg + (size_t)grow * D + ((q - 32) << 2)));
            }
            *(float4*)(sinp + r * IRS + (q << 2)) = v;
        }
        __syncthreads();

        unsigned long long acc[32];
#pragma unroll
        for (int i = 0; i < 32; i++) acc[i] = 0ull;

        const float* a0 = sinp + r0 * IRS;
        for (int k = 0; k < KTOT; k += 2) {
            float2 a2[8];
#pragma unroll
            for (int r = 0; r < 8; r++)
                a2[r] = *(const float2*)(a0 + r * IRS + k);

            const float* wk0 = sw + (k << 7) + j0;
            ulonglong2 wA0 = *(const ulonglong2*)(wk0);
            ulonglong2 wB0 = *(const ulonglong2*)(wk0 + 4);
            const float* wk1 = wk0 + D;
            ulonglong2 wA1 = *(const ulonglong2*)(wk1);
            ulonglong2 wB1 = *(const ulonglong2*)(wk1 + 4);
#pragma unroll
            for (int r = 0; r < 8; r++) {
                unsigned long long av0 = pack2(a2[r].x);
                acc[r * 4 + 0] = ffma2(av0, wA0.x, acc[r * 4 + 0]);
                acc[r * 4 + 1] = ffma2(av0, wA0.y, acc[r * 4 + 1]);
                acc[r * 4 + 2] = ffma2(av0, wB0.x, acc[r * 4 + 2]);
                acc[r * 4 + 3] = ffma2(av0, wB0.y, acc[r * 4 + 3]);
            }
#pragma unroll
            for (int r = 0; r < 8; r++) {
                unsigned long long av1 = pack2(a2[r].y);
                acc[r * 4 + 0] = ffma2(av1, wA1.x, acc[r * 4 + 0]);
                acc[r * 4 + 1] = ffma2(av1, wA1.y, acc[r * 4 + 1]);
                acc[r * 4 + 2] = ffma2(av1, wB1.x, acc[r * 4 + 2]);
                acc[r * 4 + 3] = ffma2(av1, wB1.y, acc[r * 4 + 3]);
            }
        }

#pragma unroll
        for (int r = 0; r < 8; ++r) {
            float v[8];
            float2 t;
            t = unpack2(acc[r * 4 + 0]); v[0] = t.x; v[1] = t.y;
            t = unpack2(acc[r * 4 + 1]); v[2] = t.x; v[3] = t.y;
            t = unpack2(acc[r * 4 + 2]); v[4] = t.x; v[5] = t.y;
            t = unpack2(acc[r * 4 + 3]); v[6] = t.x; v[7] = t.y;
#pragma unroll
            for (int c = 0; c < 8; c++) v[c] += sb[j0 + c];

            float scale = 1.0f;
            if (do_norm) {
                float ss = 0.f;
#pragma unroll
                for (int c = 0; c < 8; c++) ss += v[c] * v[c];
#pragma unroll
                for (int m = 8; m >= 1; m >>= 1)
                    ss += __shfl_xor_sync(0xffffffffu, ss, m);
                scale = 1.0f / fmaxf(sqrtf(ss), 1e-12f);
            }

            int grow = row0 + r0 + r;
            if (grow < N_NODES) {
                float* op = out + (size_t)grow * D + j0;
                float4 o;
                o.x = v[0] * scale; o.y = v[1] * scale;
                o.z = v[2] * scale; o.w = v[3] * scale;
                if (do_norm) __stcs((float4*)op, o); else *(float4*)op = o;
                o.x = v[4] * scale; o.y = v[5] * scale;
                o.z = v[6] * scale; o.w = v[7] * scale;
                if (do_norm) __stcs((float4*)(op + 4), o); else *(float4*)(op + 4) = o;
            }
        }
        __syncthreads();
    }
}

// ---------------- launch ----------------
extern "C" void kernel_launch(void* const* d_in, const int* in_sizes, int n_in,
                              void* d_out, int out_size) {
    const float* x   = (const float*)d_in[0];
    const int* src   = (const int*)d_in[1];
    const int* dst   = (const int*)d_in[2];
    const float* Ws1 = (const float*)d_in[3];
    const float* Wn1 = (const float*)d_in[4];
    const float* b1  = (const float*)d_in[5];
    const float* Ws2 = (const float*)d_in[6];
    const float* Wn2 = (const float*)d_in[7];
    const float* b2  = (const float*)d_in[8];
    float* out = (float*)d_out;

    float* agg;   cudaGetSymbolAddress((void**)&agg, g_agg);
    float* h1;    cudaGetSymbolAddress((void**)&h1, g_h1);
    float* wcat1; cudaGetSymbolAddress((void**)&wcat1, g_wcat1);
    float* wcat2; cudaGetSymbolAddress((void**)&wcat2, g_wcat2);
    int* degi;    cudaGetSymbolAddress((void**)&degi, g_degi);
    int* rowst;   cudaGetSymbolAddress((void**)&rowst, g_rowstart);
    int* cursor;  cudaGetSymbolAddress((void**)&cursor, g_cursor);
    int* col;     cudaGetSymbolAddress((void**)&col, g_col);
    int* bsum;    cudaGetSymbolAddress((void**)&bsum, g_bsum);
    int* boff;    cudaGetSymbolAddress((void**)&boff, g_boff);

    int sms = 148;
    cudaDeviceGetAttribute(&sms, cudaDevAttrMultiProcessorCount, 0);
    cudaFuncSetAttribute(sage_gemm_kernel,
                         cudaFuncAttributeMaxDynamicSharedMemorySize, SMEM_BYTES);

    // ---- CSR build ----
    zeroi_kernel<<<(N_NODES + 255) / 256, 256>>>(degi, N_NODES);
    degi_kernel<<<(N_EDGES + 255) / 256, 256>>>(dst, degi);
    blocksum_kernel<<<NBLK_SCAN, SCAN_CHUNK>>>(degi, bsum);
    scanbsum_kernel<<<1, 512>>>(bsum, boff);
    scanfinal_kernel<<<NBLK_SCAN, SCAN_CHUNK>>>(degi, boff, rowst, cursor);
    fill_kernel<<<(N_EDGES + 255) / 256, 256>>>(src, dst, cursor, col);

    // ---- weight transposes ----
    wcat_kernel<<<(KTOT * D + 255) / 256, 256>>>(Ws1, Wn1, wcat1);
    wcat_kernel<<<(KTOT * D + 255) / 256, 256>>>(Ws2, Wn2, wcat2);

    const int GATHER_BLOCKS = (N_NODES * 32 + 255) / 256;

    // ---- layer 1 ----
    gather_kernel<<<GATHER_BLOCKS, 256>>>(x, rowst, degi, col, agg);
    sage_gemm_kernel<<<sms, GEMM_THREADS, SMEM_BYTES>>>(x, wcat1, b1, agg, h1, 0);

    // ---- layer 2 ----
    gather_kernel<<<GATHER_BLOCKS, 256>>>(h1, rowst, degi, col, agg);
    sage_gemm_kernel<<<sms, GEMM_THREADS, SMEM_BYTES>>>(h1, wcat2, b2, agg, out, 1);
}